// round 3
// baseline (speedup 1.0000x reference)
#include <cuda_runtime.h>
#include <cstdint>
#include <math.h>

// ---------------- problem constants ----------------
// B=32, C=320, H=W=64, CTX_DIM=1024, CTX_HW=16
// conv1: in 1026 ch (pad->1040), out 320, 3x3, on 16x16
// conv2: in 320, out 320, 3x3, on 16x16

#define SWS 146   // smem weight row stride (floats); 146%32=18 -> near-conflict-free A loads, float2-aligned

// ---------------- device scratch (no allocations allowed) ----------------
__device__ float g_ctx[32 * 1040 * 256];   // tf32-rounded ctx, channel-major, padded
__device__ float g_w1 [320 * 9360];        // tf32 w_in, [co][ci*9+t], ci padded to 1040
__device__ float g_w2 [320 * 2880];        // tf32 w_out, [co][ci*9+t]
__device__ float g_mid[32 * 320 * 256];    // tf32-rounded silu(conv1+b_in)
__device__ float g_cx [32 * 320 * 256];    // conv2 + b_out (fp32)
__device__ int   g_off[144];               // im2col halo offset LUT for one 16-ch chunk

__device__ __forceinline__ float to_tf32(float x) {
    uint32_t u;
    asm("cvt.rna.tf32.f32 %0, %1;" : "=r"(u) : "f"(x));
    return __uint_as_float(u);
}

__device__ __forceinline__ void mma8(float* d, const float* a, float b0, float b1) {
    asm volatile(
        "mma.sync.aligned.m16n8k8.row.col.f32.tf32.tf32.f32 "
        "{%0,%1,%2,%3}, {%4,%5,%6,%7}, {%8,%9}, {%0,%1,%2,%3};\n"
        : "+f"(d[0]), "+f"(d[1]), "+f"(d[2]), "+f"(d[3])
        : "r"(__float_as_uint(a[0])), "r"(__float_as_uint(a[1])),
          "r"(__float_as_uint(a[2])), "r"(__float_as_uint(a[3])),
          "r"(__float_as_uint(b0)),   "r"(__float_as_uint(b1)));
}

// ---------------- K0: weight prep (tf32 round + K padding) + offset LUT ----------------
__global__ void prep_weights(const float* __restrict__ w_in,
                             const float* __restrict__ w_out,
                             float* __restrict__ w1,
                             float* __restrict__ w2,
                             int* __restrict__ offs) {
    const int n1 = 320 * 9360;      // padded w1
    const int n2 = 320 * 2880;      // w2
    int i = blockIdx.x * blockDim.x + threadIdx.x;
    if (i < n1) {
        int co  = i / 9360;
        int rem = i - co * 9360;
        int ci  = rem / 9;
        int t   = rem - ci * 9;
        float v = 0.f;
        if (ci < 1026) v = to_tf32(w_in[co * 9234 + ci * 9 + t]);
        w1[i] = v;
    } else if (i < n1 + n2) {
        int j = i - n1;
        w2[j] = to_tf32(w_out[j]);
    } else if (i < n1 + n2 + 144) {
        int k  = i - n1 - n2;
        int ci = k / 9;
        int t  = k - ci * 9;
        offs[k] = ci * 180 + (t / 3) * 18 + (t % 3);
    }
}

// ---------------- K1: build channel-major ctx (transpose) + indicator + zero pad ----------------
__global__ void build_ctx(const float* __restrict__ ctx,   // (B,256,1024)
                          const float* __restrict__ ind,   // (B,2)
                          float* __restrict__ out) {       // (B,1040,256)
    __shared__ float t[32][33];
    int b   = blockIdx.z;
    int ci0 = blockIdx.y * 32;           // 0..1055 (33 tiles)
    int pp0 = blockIdx.x * 32;           // 0..224
    int tx  = threadIdx.x & 31;
    int ty  = threadIdx.x >> 5;          // 0..7
    #pragma unroll
    for (int j = 0; j < 4; j++) {
        int pl = ty * 4 + j;             // pixel-local 0..31
        int p  = pp0 + pl;
        int ci = ci0 + tx;
        float v;
        if (ci < 1024)      v = ctx[((size_t)b * 256 + p) * 1024 + ci];
        else if (ci < 1026) v = ind[b * 2 + (ci - 1024)];
        else                v = 0.f;
        t[pl][tx] = to_tf32(v);
    }
    __syncthreads();
    #pragma unroll
    for (int j = 0; j < 4; j++) {
        int cil = ty * 4 + j;
        int ci  = ci0 + cil;
        if (ci < 1040)
            out[((size_t)b * 1040 + ci) * 256 + pp0 + tx] = t[tx][cil];
    }
}

// ---------------- GEMM conv kernel (implicit im2col, mma.sync tf32) ----------------
// Block: 64 co x 128 px, 256 threads (8 warps: 2m x 4n, warptile 32x32).
// K loop: chunks of 16 input channels (144 k values / 18 mma k-steps).
template <bool SILU>
__global__ __launch_bounds__(256, 2)
void conv_gemm(const float* __restrict__ gW, int KROW, int nchunk,
               const float* __restrict__ gX, int CIPAD,
               const float* __restrict__ bias,
               const int* __restrict__ goff,
               float* __restrict__ gOut) {
    __shared__ float sW[64 * SWS];   // 37376 B
    __shared__ float sH[16 * 180];   // 11520 B  (total 48896 <= 48KB static)

    int tid  = threadIdx.x;
    int lane = tid & 31;
    int warp = tid >> 5;
    int g    = lane >> 2;    // 0..7
    int r    = lane & 3;     // 0..3
    int mw   = warp & 1;     // m-subtile
    int nw   = warp >> 1;    // n-subtile

    int b   = blockIdx.z;
    int co0 = blockIdx.y * 64;
    int pxt = blockIdx.x;          // 0..1
    int p0  = pxt * 128;
    int yr0 = pxt * 8;

    // per-thread pixel offsets into halo (py*18 + x)
    int poff[4];
    #pragma unroll
    for (int ni = 0; ni < 4; ni++) {
        int pl = nw * 32 + ni * 8 + g;     // 0..127
        poff[ni] = (pl >> 4) * 18 + (pl & 15);
    }

    float acc[2][4][4];
    #pragma unroll
    for (int mi = 0; mi < 2; mi++)
        #pragma unroll
        for (int ni = 0; ni < 4; ni++)
            #pragma unroll
            for (int j = 0; j < 4; j++) acc[mi][ni][j] = 0.f;

    // staging assignments
    int srow = tid >> 2;                 // 0..63 (co-local row)
    int scol = (tid & 3) * 36;           // 0/36/72/108
    const float* wsrc = gW + (size_t)(co0 + srow) * KROW + scol;
    float*       wdst = sW + srow * SWS + scol;
    const float* xb   = gX + (size_t)b * CIPAD * 256;

    for (int c = 0; c < nchunk; ++c) {
        // --- stage weights: 64 x 144 (float2) ---
        {
            const float2* ws = (const float2*)(wsrc + c * 144);
            float2* wd = (float2*)wdst;
            #pragma unroll
            for (int i = 0; i < 18; i++) wd[i] = ws[i];
        }
        // --- stage halo: 16 ch x 10 rows x 18 cols (zero padded) ---
        #pragma unroll
        for (int t = 0; t < 12; t++) {
            int idx = tid + t * 256;
            if (idx < 2880) {
                int ci  = idx / 180;
                int rem = idx - ci * 180;
                int ry  = rem / 18;
                int rx  = rem - ry * 18;
                int gy  = yr0 - 1 + ry;
                int gx  = rx - 1;
                float v = 0.f;
                if ((unsigned)gy < 16u && (unsigned)gx < 16u)
                    v = xb[(size_t)(c * 16 + ci) * 256 + gy * 16 + gx];
                sH[idx] = v;
            }
        }
        __syncthreads();

        // --- 18 k-steps of 8 ---
        #pragma unroll 2
        for (int ks = 0; ks < 18; ks++) {
            int kb = ks * 8;
            float a[2][4];
            #pragma unroll
            for (int mi = 0; mi < 2; mi++) {
                const float* ab = sW + (mw * 32 + mi * 16 + g) * SWS + kb + r;
                a[mi][0] = ab[0];
                a[mi][1] = ab[8 * SWS];
                a[mi][2] = ab[4];
                a[mi][3] = ab[8 * SWS + 4];
            }
            int ob0 = __ldg(goff + kb + r);
            int ob1 = __ldg(goff + kb + r + 4);
            #pragma unroll
            for (int ni = 0; ni < 4; ni++) {
                float b0 = sH[ob0 + poff[ni]];
                float b1 = sH[ob1 + poff[ni]];
                mma8(acc[0][ni], a[0], b0, b1);
                mma8(acc[1][ni], a[1], b0, b1);
            }
        }
        __syncthreads();
    }

    // --- epilogue: bias (+ silu + tf32 round for GEMM1) ---
    float* ob = gOut + (size_t)b * 320 * 256;
    #pragma unroll
    for (int mi = 0; mi < 2; mi++) {
        #pragma unroll
        for (int half = 0; half < 2; half++) {
            int m = co0 + mw * 32 + mi * 16 + g + half * 8;
            float bz = bias[m];
            #pragma unroll
            for (int ni = 0; ni < 4; ni++) {
                int p = p0 + nw * 32 + ni * 8 + 2 * r;
                float v0 = acc[mi][ni][half * 2 + 0] + bz;
                float v1 = acc[mi][ni][half * 2 + 1] + bz;
                if (SILU) {
                    v0 = to_tf32(v0 / (1.f + expf(-v0)));
                    v1 = to_tf32(v1 / (1.f + expf(-v1)));
                }
                *(float2*)(ob + (size_t)m * 256 + p) = make_float2(v0, v1);
            }
        }
    }
}

// ---------------- K4: bbox scatter-add into output ----------------
__global__ void scatter_add(const float* __restrict__ gx,
                            const float* __restrict__ cx,
                            const float* __restrict__ bbox,
                            float* __restrict__ out) {
    int i = blockIdx.x * blockDim.x + threadIdx.x;   // exactly 10,485,760 threads
    int b    = i / 327680;                // 320*64*16 quads per batch
    int rem  = i - b * 327680;
    int ch   = rem >> 10;
    int rem2 = rem & 1023;
    int y    = rem2 >> 4;
    int x0   = (rem2 & 15) << 2;

    float4 gv = *(const float4*)(gx + (size_t)i * 4);
    float o[4] = {gv.x, gv.y, gv.z, gv.w};

    int x1  = (int)(bbox[b * 4 + 0] * 64.f);
    int y1  = (int)(bbox[b * 4 + 1] * 64.f);
    int x2i = (int)(bbox[b * 4 + 2] * 64.f);
    int y2i = (int)(bbox[b * 4 + 3] * 64.f);
    int x2 = x2i > x1 + 1 ? x2i : x1 + 1;
    int y2 = y2i > y1 + 1 ? y2i : y1 + 1;
    bool ok = (y2 <= 64) && (x2 <= 64) && (y1 >= 0) && (x1 >= 0);

    if (ok && y >= y1 && y < y2) {
        int sy = ((y - y1) * 16) / (y2 - y1);
        sy = sy < 0 ? 0 : (sy > 15 ? 15 : sy);
        const float* row = cx + ((size_t)b * 320 + ch) * 256 + sy * 16;
        #pragma unroll
        for (int e = 0; e < 4; e++) {
            int x = x0 + e;
            if (x >= x1 && x < x2) {
                int sx = ((x - x1) * 16) / (x2 - x1);
                sx = sx < 0 ? 0 : (sx > 15 ? 15 : sx);
                o[e] += row[sx];
            }
        }
    }
    *(float4*)(out + (size_t)i * 4) = make_float4(o[0], o[1], o[2], o[3]);
}

// ---------------- launcher ----------------
extern "C" void kernel_launch(void* const* d_in, const int* in_sizes, int n_in,
                              void* d_out, int out_size) {
    (void)in_sizes; (void)n_in; (void)out_size;
    const float* global_x  = (const float*)d_in[0];
    const float* context   = (const float*)d_in[1];
    const float* indicator = (const float*)d_in[2];
    const float* bbox      = (const float*)d_in[3];
    const float* w_in      = (const float*)d_in[4];
    const float* b_in      = (const float*)d_in[5];
    const float* w_out     = (const float*)d_in[6];
    const float* b_out     = (const float*)d_in[7];
    float* out = (float*)d_out;

    float *pctx, *pw1, *pw2, *pmid, *pcx;
    int* poff;
    cudaGetSymbolAddress((void**)&pctx, g_ctx);
    cudaGetSymbolAddress((void**)&pw1,  g_w1);
    cudaGetSymbolAddress((void**)&pw2,  g_w2);
    cudaGetSymbolAddress((void**)&pmid, g_mid);
    cudaGetSymbolAddress((void**)&pcx,  g_cx);
    cudaGetSymbolAddress((void**)&poff, g_off);

    const int nprep = 320 * 9360 + 320 * 2880 + 144;
    prep_weights<<<(nprep + 255) / 256, 256>>>(w_in, w_out, pw1, pw2, poff);
    build_ctx<<<dim3(8, 33, 32), 256>>>(context, indicator, pctx);
    conv_gemm<true ><<<dim3(2, 5, 32), 256>>>(pw1, 9360, 65, pctx, 1040, b_in,  poff, pmid);
    conv_gemm<false><<<dim3(2, 5, 32), 256>>>(pw2, 2880, 20, pmid,  320, b_out, poff, pcx);
    scatter_add<<<40960, 256>>>(global_x, pcx, bbox, out);
}

// round 7
// speedup vs baseline: 1.3760x; 1.3760x over previous
#include <cuda_runtime.h>
#include <cstdint>
#include <math.h>

// ---------------- problem constants ----------------
// B=32, C=320 (5 co-tiles of 64), H=W=64, CTX_DIM=1024, CTX_HW=16
// GEMM1: K = 1026*9 -> pad 1040 ch = 65 chunks of 16 ch (144 k each)
// GEMM2: K = 320*9  = 2880      -> 20 chunks
#define NCH1 65
#define NCH2 20
#define CHW  9216      // floats per weight chunk tile (4 mg * 18 ks * 32 lanes * 4)

// smem layout (bytes, dynamic)
#define SMW   36864    // weight tile 9216 floats
#define SMH   20736    // halo tile 16ch * 18 * 18 floats
#define SMBUF 57600    // SMW + SMH
#define SMLUT 115200   // 72 * int2
#define SMREQ 115776

// ---------------- device scratch ----------------
__device__ float g_ctx[32 * 1040 * 256];            // tf32 ctx, channel-major, zero-padded
__device__ float g_w1f[5 * NCH1 * CHW];             // fragment-ordered tf32 w_in
__device__ float g_w2f[5 * NCH2 * CHW];             // fragment-ordered tf32 w_out
__device__ float g_mid[32 * 320 * 256];             // tf32 silu(conv1)
__device__ float g_cx [32 * 320 * 256];             // conv2 out

__device__ __forceinline__ float to_tf32(float x) {
    uint32_t u;
    asm("cvt.rna.tf32.f32 %0, %1;" : "=r"(u) : "f"(x));
    return __uint_as_float(u);
}

__device__ __forceinline__ uint32_t smem_u32(const void* p) {
    uint32_t a;
    asm("{ .reg .u64 t; cvta.to.shared.u64 t, %1; cvt.u32.u64 %0, t; }" : "=r"(a) : "l"(p));
    return a;
}

__device__ __forceinline__ void cp16(uint32_t d, const void* s) {
    asm volatile("cp.async.cg.shared.global [%0], [%1], 16;" :: "r"(d), "l"(s));
}
__device__ __forceinline__ void cp4z(uint32_t d, const void* s, int sz) {
    asm volatile("cp.async.ca.shared.global [%0], [%1], 4, %2;" :: "r"(d), "l"(s), "r"(sz));
}
#define CP_COMMIT() asm volatile("cp.async.commit_group;" ::: "memory")
#define CP_WAIT0()  asm volatile("cp.async.wait_group 0;" ::: "memory")

__device__ __forceinline__ void mma8(float* d, const float* a, float b0, float b1) {
    asm volatile(
        "mma.sync.aligned.m16n8k8.row.col.f32.tf32.tf32.f32 "
        "{%0,%1,%2,%3}, {%4,%5,%6,%7}, {%8,%9}, {%0,%1,%2,%3};\n"
        : "+f"(d[0]), "+f"(d[1]), "+f"(d[2]), "+f"(d[3])
        : "r"(__float_as_uint(a[0])), "r"(__float_as_uint(a[1])),
          "r"(__float_as_uint(a[2])), "r"(__float_as_uint(a[3])),
          "r"(__float_as_uint(b0)),   "r"(__float_as_uint(b1)));
}

// ---------------- K0: weight prep -> fragment-ordered tiles ----------------
// layout: [cot][chunk][mg][ks][lane]{e0..e3}, e = {(g,r),(g+8,r),(g,r+4),(g+8,r+4)}
__global__ void prep_w(const float* __restrict__ w_in, const float* __restrict__ w_out,
                       float* __restrict__ w1f, float* __restrict__ w2f) {
    const int N1 = 5 * NCH1 * CHW;
    const int N2 = 5 * NCH2 * CHW;
    int i = blockIdx.x * blockDim.x + threadIdx.x;
    if (i < N1 + N2) {
        bool first = (i < N1);
        int j = first ? i : i - N1;
        int NCH = first ? NCH1 : NCH2;
        int e = j & 3, lane = (j >> 2) & 31;
        int j1 = j >> 7;
        int ks = j1 % 18;
        int j2 = j1 / 18;
        int mg = j2 & 3;
        int j3 = j2 >> 2;
        int chunk = j3 % NCH, cot = j3 / NCH;
        int g = lane >> 2, r = lane & 3;
        int row = cot * 64 + mg * 16 + g + (e & 1) * 8;
        int k   = chunk * 144 + ks * 8 + r + (e >> 1) * 4;
        int ci = k / 9, t = k - ci * 9;
        float v = 0.f;
        if (first) {
            if (ci < 1026) v = to_tf32(w_in[(row * 1026 + ci) * 9 + t]);
            w1f[j] = v;
        } else {
            v = to_tf32(w_out[(row * 320 + ci) * 9 + t]);   // ci < 320 always
            w2f[j] = v;
        }
    }
}

// ---------------- K1: channel-major ctx + indicator + zero pad ----------------
__global__ void build_ctx(const float* __restrict__ ctx, const float* __restrict__ ind,
                          float* __restrict__ out) {
    __shared__ float t[32][33];
    int b = blockIdx.z, ci0 = blockIdx.y * 32, pp0 = blockIdx.x * 32;
    int tx = threadIdx.x & 31, ty = threadIdx.x >> 5;
    #pragma unroll
    for (int j = 0; j < 4; j++) {
        int pl = ty * 4 + j, p = pp0 + pl, ci = ci0 + tx;
        float v;
        if (ci < 1024)      v = ctx[((size_t)b * 256 + p) * 1024 + ci];
        else if (ci < 1026) v = ind[b * 2 + (ci - 1024)];
        else                v = 0.f;
        t[pl][tx] = to_tf32(v);
    }
    __syncthreads();
    #pragma unroll
    for (int j = 0; j < 4; j++) {
        int cil = ty * 4 + j, ci = ci0 + cil;
        if (ci < 1040)
            out[((size_t)b * 1040 + ci) * 256 + pp0 + tx] = t[tx][cil];
    }
}

// ---------------- staging: one chunk into buffer (cp.async) ----------------
__device__ __forceinline__ void stage_chunk(uint32_t sb, int buf,
                                            const float* __restrict__ wchunk,
                                            const float* __restrict__ xb,
                                            int c, int tid) {
    uint32_t wdst = sb + buf * SMBUF + tid * 16;
    const float4* ws = (const float4*)wchunk;
    #pragma unroll
    for (int i = 0; i < 4; i++)
        cp16(wdst + i * 8192, ws + tid + i * 512);
    {
        int idx = tid + 2048;
        if (idx < 2304) cp16(sb + buf * SMBUF + idx * 16, ws + idx);
    }
    // halo: 16 ch x 18 x 18, zero-padded borders
    uint32_t hdst = sb + buf * SMBUF + SMW;
    #pragma unroll
    for (int t = 0; t < 11; t++) {
        int idx = tid + t * 512;
        if (idx < 5184) {
            int ci  = idx / 324;
            int rem = idx - ci * 324;
            int ry  = rem / 18;
            int rx  = rem - ry * 18;
            int gy = ry - 1, gx = rx - 1;
            bool ok = ((unsigned)gy < 16u) && ((unsigned)gx < 16u);
            const float* src = ok ? xb + (size_t)(c * 16 + ci) * 256 + gy * 16 + gx : xb;
            cp4z(hdst + idx * 4, src, ok ? 4 : 0);
        }
    }
    CP_COMMIT();
}

// ---------------- conv as implicit-im2col GEMM (mma.sync tf32) ----------------
// one CTA = 64 co x 256 px (one batch), 512 threads = 16 warps (2m x 8n), warptile 32x32
template <bool SILU>
__global__ __launch_bounds__(512, 1)
void conv_gemm(const float* __restrict__ gW, int nch,
               const float* __restrict__ gX, int cip,
               const float* __restrict__ bias,
               float* __restrict__ gOut) {
    extern __shared__ char dsm[];
    uint32_t sb = smem_u32(dsm);

    int tid  = threadIdx.x;
    int lane = tid & 31;
    int warp = tid >> 5;
    int g    = lane >> 2;
    int r    = lane & 3;
    int mw   = warp & 1;
    int nw   = warp >> 1;            // 0..7

    int cot   = blockIdx.x;          // 0..4
    int batch = blockIdx.y;
    const float* xb  = gX + (size_t)batch * cip * 256;
    const float* wct = gW + (size_t)cot * nch * CHW;

    // build paired halo-offset LUT: [ks*4+r] -> {off(ks*8+r), off(ks*8+r+4)}
    if (tid < 72) {
        int ks = tid >> 2, rr = tid & 3;
        int k0 = ks * 8 + rr;
        int c0 = k0 / 9, t0 = k0 - c0 * 9;
        int k1 = k0 + 4;
        int c1 = k1 / 9, t1 = k1 - c1 * 9;
        int2 v;
        v.x = c0 * 324 + (t0 / 3) * 18 + (t0 % 3);
        v.y = c1 * 324 + (t1 / 3) * 18 + (t1 % 3);
        *(int2*)(dsm + SMLUT + tid * 8) = v;
    }

    // per-thread pixel offsets into halo (row-major 18-wide)
    int poff[4];
    #pragma unroll
    for (int ni = 0; ni < 4; ni++) {
        int pl = nw * 32 + ni * 8 + g;        // 0..255
        poff[ni] = (pl >> 4) * 18 + (pl & 15);
    }

    float acc[2][4][4];
    #pragma unroll
    for (int mi = 0; mi < 2; mi++)
        #pragma unroll
        for (int ni = 0; ni < 4; ni++)
            #pragma unroll
            for (int j = 0; j < 4; j++) acc[mi][ni][j] = 0.f;

    stage_chunk(sb, 0, wct, xb, 0, tid);

    for (int c = 0; c < nch; ++c) {
        int buf = c & 1;
        CP_WAIT0();
        __syncthreads();
        if (c + 1 < nch)
            stage_chunk(sb, buf ^ 1, wct + (size_t)(c + 1) * CHW, xb, c + 1, tid);

        const float4* sWf = (const float4*)(dsm + buf * SMBUF);
        const float*  sH  = (const float*)(dsm + buf * SMBUF + SMW);
        const int2*   sL  = (const int2*)(dsm + SMLUT);

        #pragma unroll 6
        for (int ks = 0; ks < 18; ks++) {
            float4 a0 = sWf[((mw * 2 + 0) * 18 + ks) * 32 + lane];
            float4 a1 = sWf[((mw * 2 + 1) * 18 + ks) * 32 + lane];
            int2  ob  = sL[ks * 4 + r];
            #pragma unroll
            for (int ni = 0; ni < 4; ni++) {
                float b0 = sH[ob.x + poff[ni]];
                float b1 = sH[ob.y + poff[ni]];
                mma8(acc[0][ni], (const float*)&a0, b0, b1);
                mma8(acc[1][ni], (const float*)&a1, b0, b1);
            }
        }
        __syncthreads();
    }

    // epilogue: bias (+ silu + tf32 round for GEMM1)
    float* ob = gOut + (size_t)batch * 320 * 256;
    int co0 = cot * 64;
    #pragma unroll
    for (int mi = 0; mi < 2; mi++) {
        #pragma unroll
        for (int half = 0; half < 2; half++) {
            int m = co0 + mw * 32 + mi * 16 + g + half * 8;
            float bz = __ldg(bias + m);
            #pragma unroll
            for (int ni = 0; ni < 4; ni++) {
                int p = nw * 32 + ni * 8 + 2 * r;
                float v0 = acc[mi][ni][half * 2 + 0] + bz;
                float v1 = acc[mi][ni][half * 2 + 1] + bz;
                if (SILU) {
                    v0 = to_tf32(v0 / (1.f + expf(-v0)));
                    v1 = to_tf32(v1 / (1.f + expf(-v1)));
                }
                *(float2*)(ob + (size_t)m * 256 + p) = make_float2(v0, v1);
            }
        }
    }
}

// ---------------- K4: bbox scatter-add ----------------
__global__ void scatter_add(const float* __restrict__ gx, const float* __restrict__ cx,
                            const float* __restrict__ bbox, float* __restrict__ out) {
    int i = blockIdx.x * blockDim.x + threadIdx.x;
    int b = i / 327680;
    int rem = i - b * 327680;
    int ch = rem >> 10;
    int rem2 = rem & 1023;
    int y = rem2 >> 4;
    int x0 = (rem2 & 15) << 2;

    float4 gv = *(const float4*)(gx + (size_t)i * 4);
    float o[4] = {gv.x, gv.y, gv.z, gv.w};

    int x1  = (int)(bbox[b * 4 + 0] * 64.f);
    int y1  = (int)(bbox[b * 4 + 1] * 64.f);
    int x2i = (int)(bbox[b * 4 + 2] * 64.f);
    int y2i = (int)(bbox[b * 4 + 3] * 64.f);
    int x2 = x2i > x1 + 1 ? x2i : x1 + 1;
    int y2 = y2i > y1 + 1 ? y2i : y1 + 1;
    bool ok = (y2 <= 64) && (x2 <= 64) && (y1 >= 0) && (x1 >= 0);

    if (ok && y >= y1 && y < y2) {
        int sy = ((y - y1) * 16) / (y2 - y1);
        sy = sy < 0 ? 0 : (sy > 15 ? 15 : sy);
        const float* row = cx + ((size_t)b * 320 + ch) * 256 + sy * 16;
        #pragma unroll
        for (int e = 0; e < 4; e++) {
            int x = x0 + e;
            if (x >= x1 && x < x2) {
                int sx = ((x - x1) * 16) / (x2 - x1);
                sx = sx < 0 ? 0 : (sx > 15 ? 15 : sx);
                o[e] += row[sx];
            }
        }
    }
    *(float4*)(out + (size_t)i * 4) = make_float4(o[0], o[1], o[2], o[3]);
}

// ---------------- launcher ----------------
extern "C" void kernel_launch(void* const* d_in, const int* in_sizes, int n_in,
                              void* d_out, int out_size) {
    (void)in_sizes; (void)n_in; (void)out_size;
    const float* global_x  = (const float*)d_in[0];
    const float* context   = (const float*)d_in[1];
    const float* indicator = (const float*)d_in[2];
    const float* bbox      = (const float*)d_in[3];
    const float* w_in      = (const float*)d_in[4];
    const float* b_in      = (const float*)d_in[5];
    const float* w_out     = (const float*)d_in[6];
    const float* b_out     = (const float*)d_in[7];
    float* out = (float*)d_out;

    float *pctx, *pw1, *pw2, *pmid, *pcx;
    cudaGetSymbolAddress((void**)&pctx, g_ctx);
    cudaGetSymbolAddress((void**)&pw1,  g_w1f);
    cudaGetSymbolAddress((void**)&pw2,  g_w2f);
    cudaGetSymbolAddress((void**)&pmid, g_mid);
    cudaGetSymbolAddress((void**)&pcx,  g_cx);

    cudaFuncSetAttribute(conv_gemm<true >, cudaFuncAttributeMaxDynamicSharedMemorySize, SMREQ);
    cudaFuncSetAttribute(conv_gemm<false>, cudaFuncAttributeMaxDynamicSharedMemorySize, SMREQ);

    const int nprep = 5 * NCH1 * CHW + 5 * NCH2 * CHW;
    prep_w<<<(nprep + 255) / 256, 256>>>(w_in, w_out, pw1, pw2);
    build_ctx<<<dim3(8, 33, 32), 256>>>(context, indicator, pctx);
    conv_gemm<true ><<<dim3(5, 32), 512, SMREQ>>>(pw1, NCH1, pctx, 1040, b_in,  pmid);
    conv_gemm<false><<<dim3(5, 32), 512, SMREQ>>>(pw2, NCH2, pmid,  320, b_out, pcx);
    scatter_add<<<40960, 256>>>(global_x, pcx, bbox, out);
}

// round 10
// speedup vs baseline: 1.7749x; 1.2899x over previous
#include <cuda_runtime.h>
#include <cstdint>
#include <math.h>

// ---------------- problem constants ----------------
// B=32, C=320 (5 co-tiles of 64), H=W=64, CTX_DIM=1024, CTX_HW=16
// GEMM1: K = 1026*9 -> pad 1040 ch = 65 chunks of 16 ch (144 k each)
// GEMM2: K = 320*9  = 2880      -> 20 chunks
#define NCH1 65
#define NCH2 20
#define CHW  9216      // floats per weight chunk tile (4 mg * 18 ks * 32 lanes * 4)

// smem layout (bytes, dynamic)
#define SMW   36864    // weight tile 9216 floats
#define SMH   15360    // halo tile 16ch * 10 rows * 24 cols floats
#define SMBUF 52224    // SMW + SMH
#define SMLUT 104448   // 2*SMBUF; 72 * int2
#define SMREQ 105024

// ---------------- device scratch ----------------
__device__ float g_ctx[32 * 1040 * 256];            // tf32 ctx, channel-major, zero-padded
__device__ float g_w1f[5 * NCH1 * CHW];             // fragment-ordered tf32 w_in
__device__ float g_w2f[5 * NCH2 * CHW];             // fragment-ordered tf32 w_out
__device__ float g_mid[32 * 320 * 256];             // tf32 silu(conv1)
__device__ float g_cx [32 * 320 * 256];             // conv2 out

__device__ __forceinline__ float to_tf32(float x) {
    uint32_t u;
    asm("cvt.rna.tf32.f32 %0, %1;" : "=r"(u) : "f"(x));
    return __uint_as_float(u);
}

__device__ __forceinline__ uint32_t smem_u32(const void* p) {
    uint32_t a;
    asm("{ .reg .u64 t; cvta.to.shared.u64 t, %1; cvt.u32.u64 %0, t; }" : "=r"(a) : "l"(p));
    return a;
}

__device__ __forceinline__ void cp16(uint32_t d, const void* s) {
    asm volatile("cp.async.cg.shared.global [%0], [%1], 16;" :: "r"(d), "l"(s));
}
#define CP_COMMIT() asm volatile("cp.async.commit_group;" ::: "memory")
#define CP_WAIT0()  asm volatile("cp.async.wait_group 0;" ::: "memory")

__device__ __forceinline__ void mma8(float* d, const float* a, float b0, float b1) {
    asm volatile(
        "mma.sync.aligned.m16n8k8.row.col.f32.tf32.tf32.f32 "
        "{%0,%1,%2,%3}, {%4,%5,%6,%7}, {%8,%9}, {%0,%1,%2,%3};\n"
        : "+f"(d[0]), "+f"(d[1]), "+f"(d[2]), "+f"(d[3])
        : "r"(__float_as_uint(a[0])), "r"(__float_as_uint(a[1])),
          "r"(__float_as_uint(a[2])), "r"(__float_as_uint(a[3])),
          "r"(__float_as_uint(b0)),   "r"(__float_as_uint(b1)));
}

// ---------------- K0: weight prep -> fragment-ordered tiles ----------------
// layout: [cot][chunk][mg][ks][lane]{e0..e3}, e = {(g,r),(g+8,r),(g,r+4),(g+8,r+4)}
__global__ void prep_w(const float* __restrict__ w_in, const float* __restrict__ w_out,
                       float* __restrict__ w1f, float* __restrict__ w2f) {
    const int N1 = 5 * NCH1 * CHW;
    const int N2 = 5 * NCH2 * CHW;
    int i = blockIdx.x * blockDim.x + threadIdx.x;
    if (i < N1 + N2) {
        bool first = (i < N1);
        int j = first ? i : i - N1;
        int NCH = first ? NCH1 : NCH2;
        int e = j & 3, lane = (j >> 2) & 31;
        int j1 = j >> 7;
        int ks = j1 % 18;
        int j2 = j1 / 18;
        int mg = j2 & 3;
        int j3 = j2 >> 2;
        int chunk = j3 % NCH, cot = j3 / NCH;
        int g = lane >> 2, r = lane & 3;
        int row = cot * 64 + mg * 16 + g + (e & 1) * 8;
        int k   = chunk * 144 + ks * 8 + r + (e >> 1) * 4;
        int ci = k / 9, t = k - ci * 9;
        float v = 0.f;
        if (first) {
            if (ci < 1026) v = to_tf32(w_in[(row * 1026 + ci) * 9 + t]);
            w1f[j] = v;
        } else {
            v = to_tf32(w_out[(row * 320 + ci) * 9 + t]);   // ci < 320 always
            w2f[j] = v;
        }
    }
}

// ---------------- K1: channel-major ctx + indicator + zero pad ----------------
__global__ void build_ctx(const float* __restrict__ ctx, const float* __restrict__ ind,
                          float* __restrict__ out) {
    __shared__ float t[32][33];
    int b = blockIdx.z, ci0 = blockIdx.y * 32, pp0 = blockIdx.x * 32;
    int tx = threadIdx.x & 31, ty = threadIdx.x >> 5;
    #pragma unroll
    for (int j = 0; j < 4; j++) {
        int pl = ty * 4 + j, p = pp0 + pl, ci = ci0 + tx;
        float v;
        if (ci < 1024)      v = ctx[((size_t)b * 256 + p) * 1024 + ci];
        else if (ci < 1026) v = ind[b * 2 + (ci - 1024)];
        else                v = 0.f;
        t[pl][tx] = to_tf32(v);
    }
    __syncthreads();
    #pragma unroll
    for (int j = 0; j < 4; j++) {
        int cil = ty * 4 + j, ci = ci0 + cil;
        if (ci < 1040)
            out[((size_t)b * 1040 + ci) * 256 + pp0 + tx] = t[tx][cil];
    }
}

// ---------------- staging: one chunk into buffer (all cp.async.cg 16B) ----------------
// halo: 16 ch x 10 rows x 24 cols; interior (9 valid rows x 16 px) staged, borders
// pre-zeroed once (they are invariant across chunks).
__device__ __forceinline__ void stage_chunk(uint32_t sb, int buf,
                                            const float* __restrict__ wchunk,
                                            const float* __restrict__ xb,
                                            int c, int tid, int gyBase, int ryBase) {
    uint32_t base = sb + buf * SMBUF;
    const float4* ws = (const float4*)wchunk;
    #pragma unroll
    for (int i = 0; i < 9; i++) {
        int idx = tid + i * 256;                 // 0..2303
        cp16(base + idx * 16, ws + idx);
    }
    uint32_t hdst = base + SMW;
    #pragma unroll
    for (int i = 0; i < 3; i++) {
        int u = tid + i * 256;
        if (u < 576) {
            int ci  = u / 36;
            int rem = u - ci * 36;
            int ryp = rem >> 2;                  // 0..8 valid-row index
            int grp = rem & 3;                   // 4-px group
            int dstf = ci * 240 + (ryBase + ryp) * 24 + 4 + grp * 4;
            const float* src = xb + (size_t)(c * 16 + ci) * 256 + (gyBase + ryp) * 16 + grp * 4;
            cp16(hdst + dstf * 4, src);
        }
    }
    CP_COMMIT();
}

// ---------------- conv as implicit-im2col GEMM (mma.sync tf32) ----------------
// one CTA = 64 co x 128 px, 256 threads = 8 warps (2m x 4n), warptile 32x32, occ 2
template <bool SILU>
__global__ __launch_bounds__(256, 2)
void conv_gemm(const float* __restrict__ gW, int nch,
               const float* __restrict__ gX, int cip,
               const float* __restrict__ bias,
               float* __restrict__ gOut) {
    extern __shared__ char dsm[];
    uint32_t sb = smem_u32(dsm);

    int tid  = threadIdx.x;
    int lane = tid & 31;
    int warp = tid >> 5;
    int g    = lane >> 2;
    int r    = lane & 3;
    int mw   = warp & 1;
    int nw   = warp >> 1;            // 0..3

    int cot   = blockIdx.x;          // 0..4
    int batch = blockIdx.y;
    int pxt   = blockIdx.z;          // 0..1 (pixel-row half)
    int gyBase = pxt ? 7 : 0;        // first valid gy staged
    int ryBase = pxt ? 0 : 1;        // its halo row
    const float* xb  = gX + (size_t)batch * cip * 256;
    const float* wct = gW + (size_t)cot * nch * CHW;

    // zero both halo buffers once (borders stay zero forever)
    #pragma unroll
    for (int bf = 0; bf < 2; bf++)
        for (int i = tid; i < 3840; i += 256)
            *(float*)(dsm + bf * SMBUF + SMW + i * 4) = 0.f;

    // paired halo-offset LUT: [ks*4+r] -> {off(ks*8+r), off(ks*8+r+4)} (24-stride, +3 col shift)
    if (tid < 72) {
        int ks = tid >> 2, rr = tid & 3;
        int k0 = ks * 8 + rr;
        int c0 = k0 / 9, t0 = k0 - c0 * 9;
        int k1 = k0 + 4;
        int c1 = k1 / 9, t1 = k1 - c1 * 9;
        int2 v;
        v.x = c0 * 240 + (t0 / 3) * 24 + (t0 % 3) + 3;
        v.y = c1 * 240 + (t1 / 3) * 24 + (t1 % 3) + 3;
        *(int2*)(dsm + SMLUT + tid * 8) = v;
    }
    __syncthreads();

    // per-thread pixel offsets into halo
    int poff[4];
    #pragma unroll
    for (int ni = 0; ni < 4; ni++) {
        int pl = nw * 32 + ni * 8 + g;        // 0..127
        poff[ni] = (pl >> 4) * 24 + (pl & 15);
    }

    float acc[2][4][4];
    #pragma unroll
    for (int mi = 0; mi < 2; mi++)
        #pragma unroll
        for (int ni = 0; ni < 4; ni++)
            #pragma unroll
            for (int j = 0; j < 4; j++) acc[mi][ni][j] = 0.f;

    stage_chunk(sb, 0, wct, xb, 0, tid, gyBase, ryBase);

    for (int c = 0; c < nch; ++c) {
        int buf = c & 1;
        CP_WAIT0();
        __syncthreads();
        if (c + 1 < nch)
            stage_chunk(sb, buf ^ 1, wct + (size_t)(c + 1) * CHW, xb, c + 1, tid,
                        gyBase, ryBase);

        const float4* sWf = (const float4*)(dsm + buf * SMBUF);
        const float*  sH  = (const float*)(dsm + buf * SMBUF + SMW);
        const int2*   sL  = (const int2*)(dsm + SMLUT);

        #pragma unroll 6
        for (int ks = 0; ks < 18; ks++) {
            float4 a0 = sWf[((mw * 2 + 0) * 18 + ks) * 32 + lane];
            float4 a1 = sWf[((mw * 2 + 1) * 18 + ks) * 32 + lane];
            int2  ob  = sL[ks * 4 + r];
            #pragma unroll
            for (int ni = 0; ni < 4; ni++) {
                float b0 = sH[ob.x + poff[ni]];
                float b1 = sH[ob.y + poff[ni]];
                mma8(acc[0][ni], (const float*)&a0, b0, b1);
                mma8(acc[1][ni], (const float*)&a1, b0, b1);
            }
        }
        __syncthreads();
    }

    // epilogue: bias (+ silu + tf32 round for GEMM1)
    float* ob = gOut + (size_t)batch * 320 * 256;
    int co0 = cot * 64;
    int p0  = pxt * 128;
    #pragma unroll
    for (int mi = 0; mi < 2; mi++) {
        #pragma unroll
        for (int half = 0; half < 2; half++) {
            int m = co0 + mw * 32 + mi * 16 + g + half * 8;
            float bz = __ldg(bias + m);
            #pragma unroll
            for (int ni = 0; ni < 4; ni++) {
                int p = p0 + nw * 32 + ni * 8 + 2 * r;
                float v0 = acc[mi][ni][half * 2 + 0] + bz;
                float v1 = acc[mi][ni][half * 2 + 1] + bz;
                if (SILU) {
                    v0 = to_tf32(v0 / (1.f + expf(-v0)));
                    v1 = to_tf32(v1 / (1.f + expf(-v1)));
                }
                *(float2*)(ob + (size_t)m * 256 + p) = make_float2(v0, v1);
            }
        }
    }
}

// ---------------- K4: bbox scatter-add ----------------
__global__ void scatter_add(const float* __restrict__ gx, const float* __restrict__ cx,
                            const float* __restrict__ bbox, float* __restrict__ out) {
    int i = blockIdx.x * blockDim.x + threadIdx.x;
    int b = i / 327680;
    int rem = i - b * 327680;
    int ch = rem >> 10;
    int rem2 = rem & 1023;
    int y = rem2 >> 4;
    int x0 = (rem2 & 15) << 2;

    float4 gv = *(const float4*)(gx + (size_t)i * 4);
    float o[4] = {gv.x, gv.y, gv.z, gv.w};

    int x1  = (int)(bbox[b * 4 + 0] * 64.f);
    int y1  = (int)(bbox[b * 4 + 1] * 64.f);
    int x2i = (int)(bbox[b * 4 + 2] * 64.f);
    int y2i = (int)(bbox[b * 4 + 3] * 64.f);
    int x2 = x2i > x1 + 1 ? x2i : x1 + 1;
    int y2 = y2i > y1 + 1 ? y2i : y1 + 1;
    bool ok = (y2 <= 64) && (x2 <= 64) && (y1 >= 0) && (x1 >= 0);

    if (ok && y >= y1 && y < y2) {
        int sy = ((y - y1) * 16) / (y2 - y1);
        sy = sy < 0 ? 0 : (sy > 15 ? 15 : sy);
        const float* row = cx + ((size_t)b * 320 + ch) * 256 + sy * 16;
        #pragma unroll
        for (int e = 0; e < 4; e++) {
            int x = x0 + e;
            if (x >= x1 && x < x2) {
                int sx = ((x - x1) * 16) / (x2 - x1);
                sx = sx < 0 ? 0 : (sx > 15 ? 15 : sx);
                o[e] += row[sx];
            }
        }
    }
    *(float4*)(out + (size_t)i * 4) = make_float4(o[0], o[1], o[2], o[3]);
}

// ---------------- launcher ----------------
extern "C" void kernel_launch(void* const* d_in, const int* in_sizes, int n_in,
                              void* d_out, int out_size) {
    (void)in_sizes; (void)n_in; (void)out_size;
    const float* global_x  = (const float*)d_in[0];
    const float* context   = (const float*)d_in[1];
    const float* indicator = (const float*)d_in[2];
    const float* bbox      = (const float*)d_in[3];
    const float* w_in      = (const float*)d_in[4];
    const float* b_in      = (const float*)d_in[5];
    const float* w_out     = (const float*)d_in[6];
    const float* b_out     = (const float*)d_in[7];
    float* out = (float*)d_out;

    float *pctx, *pw1, *pw2, *pmid, *pcx;
    cudaGetSymbolAddress((void**)&pctx, g_ctx);
    cudaGetSymbolAddress((void**)&pw1,  g_w1f);
    cudaGetSymbolAddress((void**)&pw2,  g_w2f);
    cudaGetSymbolAddress((void**)&pmid, g_mid);
    cudaGetSymbolAddress((void**)&pcx,  g_cx);

    cudaFuncSetAttribute(conv_gemm<true >, cudaFuncAttributeMaxDynamicSharedMemorySize, SMREQ);
    cudaFuncSetAttribute(conv_gemm<false>, cudaFuncAttributeMaxDynamicSharedMemorySize, SMREQ);

    const int nprep = 5 * NCH1 * CHW + 5 * NCH2 * CHW;
    prep_w<<<(nprep + 255) / 256, 256>>>(w_in, w_out, pw1, pw2);
    build_ctx<<<dim3(8, 33, 32), 256>>>(context, indicator, pctx);
    conv_gemm<true ><<<dim3(5, 32, 2), 256, SMREQ>>>(pw1, NCH1, pctx, 1040, b_in,  pmid);
    conv_gemm<false><<<dim3(5, 32, 2), 256, SMREQ>>>(pw2, NCH2, pmid,  320, b_out, pcx);
    scatter_add<<<40960, 256>>>(global_x, pcx, bbox, out);
}

// round 12
// speedup vs baseline: 2.8421x; 1.6012x over previous
#include <cuda_runtime.h>
#include <cuda_fp16.h>
#include <cstdint>
#include <math.h>

// ---------------- problem constants ----------------
// B=32, C=320 (5 co-tiles of 64), H=W=64, CTX_DIM=1024, CTX_HW=16
// GEMM1: 1040 in-ch = 65 chunks of 16; GEMM2: 320 = 20 chunks
// fp16 mma m16n8k16, tap-major K: 9 k-steps per 16-ch chunk (k = 16 channels)
#define NCH1 65
#define NCH2 20
#define CHWH 9216      // halves per weight chunk tile: 4 mg * 9 t * 32 lane * 8

// smem (bytes): per buffer A tile 18432 + halo 10*24*48 = 11520
#define SMA   18432
#define SMHB  11520
#define SMBUF 29952
#define SMREQ 59904

// ---------------- device scratch ----------------
__device__ __half g_ctxh[32 * 65 * 256 * 16];   // interleaved fp16 ctx
__device__ __half g_w1h [5 * NCH1 * CHWH];      // fragment fp16 w_in
__device__ __half g_w2h [5 * NCH2 * CHWH];      // fragment fp16 w_out
__device__ __half g_midh[32 * 20 * 256 * 16];   // interleaved fp16 silu(conv1)
__device__ float  g_cx  [32 * 320 * 256];       // conv2 out (NCHW fp32)

__device__ __forceinline__ uint32_t smem_u32(const void* p) {
    uint32_t a;
    asm("{ .reg .u64 t; cvta.to.shared.u64 t, %1; cvt.u32.u64 %0, t; }" : "=r"(a) : "l"(p));
    return a;
}
__device__ __forceinline__ void cp16(uint32_t d, const void* s) {
    asm volatile("cp.async.cg.shared.global [%0], [%1], 16;" :: "r"(d), "l"(s));
}
#define CP_COMMIT() asm volatile("cp.async.commit_group;" ::: "memory")
#define CP_WAIT0()  asm volatile("cp.async.wait_group 0;" ::: "memory")

__device__ __forceinline__ void mma16(float* d, const uint4 a, const uint2 b) {
    asm volatile(
        "mma.sync.aligned.m16n8k16.row.col.f32.f16.f16.f32 "
        "{%0,%1,%2,%3}, {%4,%5,%6,%7}, {%8,%9}, {%0,%1,%2,%3};\n"
        : "+f"(d[0]), "+f"(d[1]), "+f"(d[2]), "+f"(d[3])
        : "r"(a.x), "r"(a.y), "r"(a.z), "r"(a.w), "r"(b.x), "r"(b.y));
}

// interleave position of channel ch (0..15) within a 16-ch block:
// groups j=0..3 hold {2j, 2j+1, 2j+8, 2j+9}
__host__ __device__ __forceinline__ int ipos(int ch) {
    return ((ch & 7) >> 1) * 4 + (ch & 1) + ((ch >> 3) & 1) * 2;
}

// ---------------- K0: weight prep -> fp16 fragment tiles (tap-major) ----------------
// layout: [cot][chunk][mg 4][t 9][lane 32][8 halves = a0..a3 pairs]
__global__ void prep_w(const float* __restrict__ w_in, const float* __restrict__ w_out,
                       __half* __restrict__ w1h, __half* __restrict__ w2h) {
    const int N1 = 5 * NCH1 * CHWH;
    const int N2 = 5 * NCH2 * CHWH;
    int i = blockIdx.x * blockDim.x + threadIdx.x;
    if (i >= N1 + N2) return;
    bool first = (i < N1);
    int j = first ? i : i - N1;
    int NCH = first ? NCH1 : NCH2;
    int h    = j & 7;
    int lane = (j >> 3) & 31;
    int t    = (j >> 8) % 9;
    int rest = (j >> 8) / 9;
    int mg   = rest & 3;
    int r2   = rest >> 2;
    int chunk = r2 % NCH, cot = r2 / NCH;
    int g = lane >> 2, r = lane & 3;
    int row = cot * 64 + mg * 16 + g + ((h >> 1) & 1) * 8;
    int ch  = 2 * r + (h & 1) + ((h >> 2) & 1) * 8;
    int ci  = chunk * 16 + ch;
    float v = 0.f;
    if (first) {
        if (ci < 1026) v = w_in[(row * 1026 + ci) * 9 + t];
        w1h[j] = __float2half_rn(v);
    } else {
        v = w_out[(row * 320 + ci) * 9 + t];
        w2h[j] = __float2half_rn(v);
    }
}

// ---------------- K1: ctx -> fp16 interleaved pixel-major ----------------
__global__ void build_ctx(const float* __restrict__ ctx, const float* __restrict__ ind,
                          __half* __restrict__ out) {
    __shared__ __half s[256 * 16];
    int cb = blockIdx.x, b = blockIdx.y, tid = threadIdx.x;
    int ci0 = cb * 16;
    #pragma unroll
    for (int j = 0; j < 16; j++) {
        int idx = tid + j * 256;
        int p = idx >> 4, ch = idx & 15;
        int ci = ci0 + ch;
        float v;
        if (ci < 1024)      v = ctx[((size_t)b * 256 + p) * 1024 + ci];
        else if (ci < 1026) v = ind[b * 2 + (ci - 1024)];
        else                v = 0.f;
        s[p * 16 + ipos(ch)] = __float2half_rn(v);
    }
    __syncthreads();
    const uint4* su = (const uint4*)s;
    uint4* du = (uint4*)out + ((size_t)(b * 65 + cb) * 256 + tid) * 2;
    du[0] = su[tid * 2];
    du[1] = su[tid * 2 + 1];
}

// ---------------- staging one chunk (A tile + halo interior) ----------------
__device__ __forceinline__ void stage_chunk(uint32_t sb, char* dsm, int buf,
                                            const __half* __restrict__ wchunk,
                                            const __half* __restrict__ xb,
                                            int c, int tid, int gyBase, int ryOff) {
    uint32_t base = sb + buf * SMBUF;
    const char* ws = (const char*)wchunk;
    #pragma unroll
    for (int i = 0; i < 5; i++) {
        int idx = tid + i * 256;
        if (idx < 1152) cp16(base + idx * 16, ws + idx * 16);
    }
    uint32_t hd = base + SMA;
    #pragma unroll
    for (int i = 0; i < 2; i++) {
        int idx = tid + i * 256;
        if (idx < 288) {
            int hsel = idx & 1;
            int px   = (idx >> 1) & 15;
            int ryp  = idx >> 5;                       // 0..8
            const char* src = (const char*)(xb + ((size_t)c * 256 + (gyBase + ryp) * 16 + px) * 16)
                              + hsel * 16;
            cp16(hd + ((ryp + ryOff) * 24 + px + 4) * 48 + hsel * 16, src);
        }
    }
    CP_COMMIT();
}

// ---------------- conv as implicit-im2col GEMM (mma.sync fp16 k16) ----------------
// CTA = 64 co x 128 px, 256 thr = 8 warps (2m x 4n), warptile 32x32, occ 2
template <bool SILU>
__global__ __launch_bounds__(256, 2)
void conv_gemm(const __half* __restrict__ gW, int nch,
               const __half* __restrict__ gX,
               const float* __restrict__ bias,
               void* __restrict__ gOut) {
    extern __shared__ char dsm[];
    uint32_t sb = smem_u32(dsm);

    int tid  = threadIdx.x;
    int lane = tid & 31;
    int warp = tid >> 5;
    int g    = lane >> 2;
    int r    = lane & 3;
    int mw   = warp & 1;
    int nw   = warp >> 1;            // 0..3

    int cot   = blockIdx.x;          // 0..4
    int batch = blockIdx.y;
    int pxt   = blockIdx.z;          // 0..1
    int gyBase = pxt ? 7 : 0;
    int ryOff  = pxt ? 0 : 1;

    const __half* xb  = gX + (size_t)batch * nch * 256 * 16;
    const __half* wct = gW + (size_t)cot * nch * CHWH;

    // zero both halo buffers once (borders + pad stay zero)
    for (int i = tid; i < 720; i += 256) {
        *(uint4*)(dsm + 0 * SMBUF + SMA + i * 16) = make_uint4(0, 0, 0, 0);
        *(uint4*)(dsm + 1 * SMBUF + SMA + i * 16) = make_uint4(0, 0, 0, 0);
    }
    __syncthreads();

    // per-thread B base offsets (bytes within halo)
    int pb[4];
    #pragma unroll
    for (int ni = 0; ni < 4; ni++) {
        int pl  = nw * 32 + ni * 8 + g;          // 0..127
        int pyo = pl >> 4;
        int hx  = (pl & 15) + 4;
        pb[ni] = ((pyo + 1) * 24 + hx) * 48 + r * 8;
    }

    float acc[2][4][4];
    #pragma unroll
    for (int mi = 0; mi < 2; mi++)
        #pragma unroll
        for (int ni = 0; ni < 4; ni++)
            #pragma unroll
            for (int j = 0; j < 4; j++) acc[mi][ni][j] = 0.f;

    stage_chunk(sb, dsm, 0, wct, xb, 0, tid, gyBase, ryOff);

    for (int c = 0; c < nch; ++c) {
        int buf = c & 1;
        CP_WAIT0();
        __syncthreads();
        if (c + 1 < nch)
            stage_chunk(sb, dsm, buf ^ 1, wct + (size_t)(c + 1) * CHWH, xb, c + 1,
                        tid, gyBase, ryOff);

        const uint4* sA = (const uint4*)(dsm + buf * SMBUF);
        const char*  sH = dsm + buf * SMBUF + SMA;

        #pragma unroll
        for (int t = 0; t < 9; t++) {
            int toff = (t / 3 - 1) * 1152 + (t % 3 - 1) * 48;
            uint4 a0 = sA[((mw * 2 + 0) * 9 + t) * 32 + lane];
            uint4 a1 = sA[((mw * 2 + 1) * 9 + t) * 32 + lane];
            #pragma unroll
            for (int ni = 0; ni < 4; ni++) {
                uint2 b = *(const uint2*)(sH + pb[ni] + toff);
                mma16(acc[0][ni], a0, b);
                mma16(acc[1][ni], a1, b);
            }
        }
        __syncthreads();
    }

    // ---------------- epilogue ----------------
    int co0 = cot * 64;
    int p0  = pxt * 128;
    if (SILU) {
        __half* ob = (__half*)gOut;
        #pragma unroll
        for (int mi = 0; mi < 2; mi++) {
            int cb = (batch * 20) + (cot * 4 + mw * 2 + mi);
            #pragma unroll
            for (int half = 0; half < 2; half++) {
                int m  = co0 + mw * 32 + mi * 16 + g + half * 8;
                int pos = (g >> 1) * 4 + (g & 1) + half * 2;
                float bz = __ldg(bias + m);
                #pragma unroll
                for (int ni = 0; ni < 4; ni++) {
                    int p = p0 + nw * 32 + ni * 8 + 2 * r;
                    #pragma unroll
                    for (int col = 0; col < 2; col++) {
                        float v = acc[mi][ni][half * 2 + col] + bz;
                        v = v / (1.f + expf(-v));
                        ob[((size_t)cb * 256 + p + col) * 16 + pos] = __float2half_rn(v);
                    }
                }
            }
        }
    } else {
        float* ob = (float*)gOut + (size_t)batch * 320 * 256;
        #pragma unroll
        for (int mi = 0; mi < 2; mi++) {
            #pragma unroll
            for (int half = 0; half < 2; half++) {
                int m = co0 + mw * 32 + mi * 16 + g + half * 8;
                float bz = __ldg(bias + m);
                #pragma unroll
                for (int ni = 0; ni < 4; ni++) {
                    int p = p0 + nw * 32 + ni * 8 + 2 * r;
                    float v0 = acc[mi][ni][half * 2 + 0] + bz;
                    float v1 = acc[mi][ni][half * 2 + 1] + bz;
                    *(float2*)(ob + (size_t)m * 256 + p) = make_float2(v0, v1);
                }
            }
        }
    }
}

// ---------------- K4: bbox scatter-add ----------------
__global__ void scatter_add(const float* __restrict__ gx, const float* __restrict__ cx,
                            const float* __restrict__ bbox, float* __restrict__ out) {
    int i = blockIdx.x * blockDim.x + threadIdx.x;
    int b = i / 327680;
    int rem = i - b * 327680;
    int ch = rem >> 10;
    int rem2 = rem & 1023;
    int y = rem2 >> 4;
    int x0 = (rem2 & 15) << 2;

    float4 gv = *(const float4*)(gx + (size_t)i * 4);
    float o[4] = {gv.x, gv.y, gv.z, gv.w};

    int x1  = (int)(bbox[b * 4 + 0] * 64.f);
    int y1  = (int)(bbox[b * 4 + 1] * 64.f);
    int x2i = (int)(bbox[b * 4 + 2] * 64.f);
    int y2i = (int)(bbox[b * 4 + 3] * 64.f);
    int x2 = x2i > x1 + 1 ? x2i : x1 + 1;
    int y2 = y2i > y1 + 1 ? y2i : y1 + 1;
    bool ok = (y2 <= 64) && (x2 <= 64) && (y1 >= 0) && (x1 >= 0);

    if (ok && y >= y1 && y < y2) {
        int sy = ((y - y1) * 16) / (y2 - y1);
        sy = sy < 0 ? 0 : (sy > 15 ? 15 : sy);
        const float* row = cx + ((size_t)b * 320 + ch) * 256 + sy * 16;
        #pragma unroll
        for (int e = 0; e < 4; e++) {
            int x = x0 + e;
            if (x >= x1 && x < x2) {
                int sx = ((x - x1) * 16) / (x2 - x1);
                sx = sx < 0 ? 0 : (sx > 15 ? 15 : sx);
                o[e] += row[sx];
            }
        }
    }
    *(float4*)(out + (size_t)i * 4) = make_float4(o[0], o[1], o[2], o[3]);
}

// ---------------- launcher ----------------
extern "C" void kernel_launch(void* const* d_in, const int* in_sizes, int n_in,
                              void* d_out, int out_size) {
    (void)in_sizes; (void)n_in; (void)out_size;
    const float* global_x  = (const float*)d_in[0];
    const float* context   = (const float*)d_in[1];
    const float* indicator = (const float*)d_in[2];
    const float* bbox      = (const float*)d_in[3];
    const float* w_in      = (const float*)d_in[4];
    const float* b_in      = (const float*)d_in[5];
    const float* w_out     = (const float*)d_in[6];
    const float* b_out     = (const float*)d_in[7];
    float* out = (float*)d_out;

    __half *pctx, *pw1, *pw2, *pmid;
    float *pcx;
    cudaGetSymbolAddress((void**)&pctx, g_ctxh);
    cudaGetSymbolAddress((void**)&pw1,  g_w1h);
    cudaGetSymbolAddress((void**)&pw2,  g_w2h);
    cudaGetSymbolAddress((void**)&pmid, g_midh);
    cudaGetSymbolAddress((void**)&pcx,  g_cx);

    cudaFuncSetAttribute(conv_gemm<true >, cudaFuncAttributeMaxDynamicSharedMemorySize, SMREQ);
    cudaFuncSetAttribute(conv_gemm<false>, cudaFuncAttributeMaxDynamicSharedMemorySize, SMREQ);

    const int nprep = 5 * NCH1 * CHWH + 5 * NCH2 * CHWH;
    prep_w<<<(nprep + 255) / 256, 256>>>(w_in, w_out, pw1, pw2);
    build_ctx<<<dim3(65, 32), 256>>>(context, indicator, pctx);
    conv_gemm<true ><<<dim3(5, 32, 2), 256, SMREQ>>>(pw1, NCH1, pctx, b_in,  (void*)pmid);
    conv_gemm<false><<<dim3(5, 32, 2), 256, SMREQ>>>(pw2, NCH2, pmid, b_out, (void*)pcx);
    scatter_add<<<40960, 256>>>(global_x, pcx, bbox, out);
}

// round 16
// speedup vs baseline: 3.6030x; 1.2677x over previous
#include <cuda_runtime.h>
#include <cuda_fp16.h>
#include <cstdint>
#include <math.h>

// ---------------- problem constants ----------------
// B=32, C=320 (4 co-tiles of 80), H=W=64, CTX_DIM=1024, CTX_HW=16
// GEMM1: 1040 in-ch = 65 chunks of 16; GEMM2: 320 = 20 chunks
// fp16 mma m16n8k16, tap-major K: 9 k-steps per 16-ch chunk (k = 16 channels)
#define NCH1 65
#define NCH2 20
#define CHWH 11520     // halves per weight chunk tile: 5 mi * 9 t * 32 lane * 8

// smem (bytes): per buffer A tile 23040 + halo 10*24*32 = 7680
#define SMA   23040
#define SMBUF 30720
#define SMREQ 61440

// ---------------- device scratch ----------------
__device__ __half g_ctxh[32 * 65 * 256 * 16];   // interleaved fp16 ctx
__device__ __half g_w1h [4 * NCH1 * CHWH];      // fragment fp16 w_in
__device__ __half g_w2h [4 * NCH2 * CHWH];      // fragment fp16 w_out
__device__ __half g_midh[32 * 20 * 256 * 16];   // interleaved fp16 silu(conv1)
__device__ float  g_cx  [32 * 320 * 256];       // conv2 out (NCHW fp32)

__device__ __forceinline__ uint32_t smem_u32(const void* p) {
    uint32_t a;
    asm("{ .reg .u64 t; cvta.to.shared.u64 t, %1; cvt.u32.u64 %0, t; }" : "=r"(a) : "l"(p));
    return a;
}
__device__ __forceinline__ void cp16(uint32_t d, const void* s) {
    asm volatile("cp.async.cg.shared.global [%0], [%1], 16;" :: "r"(d), "l"(s));
}
#define CP_COMMIT() asm volatile("cp.async.commit_group;" ::: "memory")
#define CP_WAIT0()  asm volatile("cp.async.wait_group 0;" ::: "memory")

__device__ __forceinline__ void mma16(float* d, const uint4 a, const uint2 b) {
    asm volatile(
        "mma.sync.aligned.m16n8k16.row.col.f32.f16.f16.f32 "
        "{%0,%1,%2,%3}, {%4,%5,%6,%7}, {%8,%9}, {%0,%1,%2,%3};\n"
        : "+f"(d[0]), "+f"(d[1]), "+f"(d[2]), "+f"(d[3])
        : "r"(a.x), "r"(a.y), "r"(a.z), "r"(a.w), "r"(b.x), "r"(b.y));
}

// interleave position of channel ch (0..15): groups j hold {2j,2j+1,2j+8,2j+9}
__host__ __device__ __forceinline__ int ipos(int ch) {
    return ((ch & 7) >> 1) * 4 + (ch & 1) + ((ch >> 3) & 1) * 2;
}

// ---------------- K0: weight prep -> fp16 fragment tiles (tap-major, M=80) ----------------
// layout: [cot 4][chunk][mi 5][t 9][lane 32][8 halves]
__global__ void prep_w(const float* __restrict__ w_in, const float* __restrict__ w_out,
                       __half* __restrict__ w1h, __half* __restrict__ w2h) {
    const int N1 = 4 * NCH1 * CHWH;
    const int N2 = 4 * NCH2 * CHWH;
    int i = blockIdx.x * blockDim.x + threadIdx.x;
    if (i >= N1 + N2) return;
    bool first = (i < N1);
    int j = first ? i : i - N1;
    int NCH = first ? NCH1 : NCH2;
    int h    = j & 7;
    int lane = (j >> 3) & 31;
    int t    = (j >> 8) % 9;
    int rest = (j >> 8) / 9;
    int mi   = rest % 5;
    int r2   = rest / 5;
    int chunk = r2 % NCH, cot = r2 / NCH;
    int g = lane >> 2, r = lane & 3;
    int row = cot * 80 + mi * 16 + g + ((h >> 1) & 1) * 8;
    int ch  = 2 * r + (h & 1) + ((h >> 2) & 1) * 8;
    int ci  = chunk * 16 + ch;
    float v = 0.f;
    if (first) {
        if (ci < 1026) v = w_in[(row * 1026 + ci) * 9 + t];
        w1h[j] = __float2half_rn(v);
    } else {
        v = w_out[(row * 320 + ci) * 9 + t];
        w2h[j] = __float2half_rn(v);
    }
}

// ---------------- K1: ctx -> fp16 interleaved pixel-major ----------------
__global__ void build_ctx(const float* __restrict__ ctx, const float* __restrict__ ind,
                          __half* __restrict__ out) {
    __shared__ __half s[256 * 16];
    int cb = blockIdx.x, b = blockIdx.y, tid = threadIdx.x;
    int ci0 = cb * 16;
    #pragma unroll
    for (int j = 0; j < 16; j++) {
        int idx = tid + j * 256;
        int p = idx >> 4, ch = idx & 15;
        int ci = ci0 + ch;
        float v;
        if (ci < 1024)      v = ctx[((size_t)b * 256 + p) * 1024 + ci];
        else if (ci < 1026) v = ind[b * 2 + (ci - 1024)];
        else                v = 0.f;
        s[p * 16 + ipos(ch)] = __float2half_rn(v);
    }
    __syncthreads();
    const uint4* su = (const uint4*)s;
    uint4* du = (uint4*)out + ((size_t)(b * 65 + cb) * 256 + tid) * 2;
    du[0] = su[tid * 2];
    du[1] = su[tid * 2 + 1];
}

// ---------------- staging one chunk (A tile + halo interior) ----------------
__device__ __forceinline__ void stage_chunk(uint32_t sb, int buf,
                                            const __half* __restrict__ wchunk,
                                            const __half* __restrict__ xb,
                                            int c, int tid, int gyBase, int ryOff) {
    uint32_t base = sb + buf * SMBUF;
    const char* ws = (const char*)wchunk;
    #pragma unroll
    for (int i = 0; i < 6; i++) {
        int idx = tid + i * 256;
        if (idx < 1440) cp16(base + idx * 16, ws + idx * 16);
    }
    uint32_t hd = base + SMA;
    #pragma unroll
    for (int i = 0; i < 2; i++) {
        int idx = tid + i * 256;
        if (idx < 288) {
            int hsel = idx & 1;
            int px   = (idx >> 1) & 15;
            int ryp  = idx >> 5;                       // 0..8
            const char* src = (const char*)(xb + ((size_t)c * 256 + (gyBase + ryp) * 16 + px) * 16)
                              + hsel * 16;
            cp16(hd + ((ryp + ryOff) * 24 + px + 4) * 32 + hsel * 16, src);
        }
    }
    CP_COMMIT();
}

// ---------------- conv as implicit-im2col GEMM (mma.sync fp16 k16) ----------------
// CTA = 80 co x 128 px, 256 thr = 8 warps (1m x 8n), warptile 80x16, occ 2
// grid (4 cot, 32 batch, 2 pxt) = 256 CTAs -> single wave at occ 2
template <bool SILU>
__global__ __launch_bounds__(256, 2)
void conv_gemm(const __half* __restrict__ gW, int nch,
               const __half* __restrict__ gX,
               const float* __restrict__ bias,
               void* __restrict__ gOut) {
    extern __shared__ char dsm[];
    uint32_t sb = smem_u32(dsm);

    int tid  = threadIdx.x;
    int lane = tid & 31;
    int nw   = tid >> 5;             // warp = n-tile 0..7
    int g    = lane >> 2;
    int r    = lane & 3;

    int cot   = blockIdx.x;          // 0..3
    int batch = blockIdx.y;
    int pxt   = blockIdx.z;          // 0..1
    int gyBase = pxt ? 7 : 0;
    int ryOff  = pxt ? 0 : 1;

    const __half* xb  = gX + (size_t)batch * nch * 256 * 16;
    const __half* wct = gW + (size_t)cot * nch * CHWH;

    // zero both halo buffers once (borders stay zero)
    #pragma unroll
    for (int i = tid; i < 480; i += 256) {
        *(uint4*)(dsm + 0 * SMBUF + SMA + i * 16) = make_uint4(0, 0, 0, 0);
        *(uint4*)(dsm + 1 * SMBUF + SMA + i * 16) = make_uint4(0, 0, 0, 0);
    }
    __syncthreads();

    // per-thread B base offsets (bytes within halo); cells are 32B, conflict-free
    int pb[2];
    #pragma unroll
    for (int nj = 0; nj < 2; nj++)
        pb[nj] = ((nw + 1) * 24 + nj * 8 + g + 4) * 32 + r * 8;

    float acc[5][2][4];
    #pragma unroll
    for (int mi = 0; mi < 5; mi++)
        #pragma unroll
        for (int nj = 0; nj < 2; nj++)
            #pragma unroll
            for (int j = 0; j < 4; j++) acc[mi][nj][j] = 0.f;

    stage_chunk(sb, 0, wct, xb, 0, tid, gyBase, ryOff);

    for (int c = 0; c < nch; ++c) {
        int buf = c & 1;
        CP_WAIT0();
        __syncthreads();
        if (c + 1 < nch)
            stage_chunk(sb, buf ^ 1, wct + (size_t)(c + 1) * CHWH, xb, c + 1,
                        tid, gyBase, ryOff);

        const uint4* sA = (const uint4*)(dsm + buf * SMBUF);
        const char*  sH = dsm + buf * SMBUF + SMA;

        #pragma unroll
        for (int t = 0; t < 9; t++) {
            int toff = (t / 3 - 1) * 768 + (t % 3 - 1) * 32;
            uint2 b0 = *(const uint2*)(sH + pb[0] + toff);
            uint2 b1 = *(const uint2*)(sH + pb[1] + toff);
            #pragma unroll
            for (int mi = 0; mi < 5; mi++) {
                uint4 a = sA[(mi * 9 + t) * 32 + lane];
                mma16(acc[mi][0], a, b0);
                mma16(acc[mi][1], a, b1);
            }
        }
        __syncthreads();
    }

    // ---------------- epilogue ----------------
    int p0 = pxt * 128 + nw * 16;
    if (SILU) {
        __half* ob = (__half*)gOut;
        #pragma unroll
        for (int mi = 0; mi < 5; mi++) {
            int cb = batch * 20 + cot * 5 + mi;
            #pragma unroll
            for (int half = 0; half < 2; half++) {
                int m   = cot * 80 + mi * 16 + g + half * 8;
                int pos = (g >> 1) * 4 + (g & 1) + half * 2;
                float bz = __ldg(bias + m);
                #pragma unroll
                for (int nj = 0; nj < 2; nj++) {
                    int p = p0 + nj * 8 + 2 * r;
                    #pragma unroll
                    for (int col = 0; col < 2; col++) {
                        float v = acc[mi][nj][half * 2 + col] + bz;
                        v = v / (1.f + expf(-v));
                        ob[((size_t)cb * 256 + p + col) * 16 + pos] = __float2half_rn(v);
                    }
                }
            }
        }
    } else {
        float* ob = (float*)gOut + (size_t)batch * 320 * 256;
        #pragma unroll
        for (int mi = 0; mi < 5; mi++) {
            #pragma unroll
            for (int half = 0; half < 2; half++) {
                int m = cot * 80 + mi * 16 + g + half * 8;
                float bz = __ldg(bias + m);
                #pragma unroll
                for (int nj = 0; nj < 2; nj++) {
                    int p = p0 + nj * 8 + 2 * r;
                    float v0 = acc[mi][nj][half * 2 + 0] + bz;
                    float v1 = acc[mi][nj][half * 2 + 1] + bz;
                    *(float2*)(ob + (size_t)m * 256 + p) = make_float2(v0, v1);
                }
            }
        }
    }
}

// ---------------- K4: bbox scatter-add ----------------
__global__ void scatter_add(const float* __restrict__ gx, const float* __restrict__ cx,
                            const float* __restrict__ bbox, float* __restrict__ out) {
    int i = blockIdx.x * blockDim.x + threadIdx.x;
    int b = i / 327680;
    int rem = i - b * 327680;
    int ch = rem >> 10;
    int rem2 = rem & 1023;
    int y = rem2 >> 4;
    int x0 = (rem2 & 15) << 2;

    float4 gv = *(const float4*)(gx + (size_t)i * 4);
    float o[4] = {gv.x, gv.y, gv.z, gv.w};

    int x1  = (int)(bbox[b * 4 + 0] * 64.f);
    int y1  = (int)(bbox[b * 4 + 1] * 64.f);
    int x2i = (int)(bbox[b * 4 + 2] * 64.f);
    int y2i = (int)(bbox[b * 4 + 3] * 64.f);
    int x2 = x2i > x1 + 1 ? x2i : x1 + 1;
    int y2 = y2i > y1 + 1 ? y2i : y1 + 1;
    bool ok = (y2 <= 64) && (x2 <= 64) && (y1 >= 0) && (x1 >= 0);

    if (ok && y >= y1 && y < y2) {
        int sy = ((y - y1) * 16) / (y2 - y1);
        sy = sy < 0 ? 0 : (sy > 15 ? 15 : sy);
        const float* row = cx + ((size_t)b * 320 + ch) * 256 + sy * 16;
        #pragma unroll
        for (int e = 0; e < 4; e++) {
            int x = x0 + e;
            if (x >= x1 && x < x2) {
                int sx = ((x - x1) * 16) / (x2 - x1);
                sx = sx < 0 ? 0 : (sx > 15 ? 15 : sx);
                o[e] += row[sx];
            }
        }
    }
    *(float4*)(out + (size_t)i * 4) = make_float4(o[0], o[1], o[2], o[3]);
}

// ---------------- launcher ----------------
extern "C" void kernel_launch(void* const* d_in, const int* in_sizes, int n_in,
                              void* d_out, int out_size) {
    (void)in_sizes; (void)n_in; (void)out_size;
    const float* global_x  = (const float*)d_in[0];
    const float* context   = (const float*)d_in[1];
    const float* indicator = (const float*)d_in[2];
    const float* bbox      = (const float*)d_in[3];
    const float* w_in      = (const float*)d_in[4];
    const float* b_in      = (const float*)d_in[5];
    const float* w_out     = (const float*)d_in[6];
    const float* b_out     = (const float*)d_in[7];
    float* out = (float*)d_out;

    __half *pctx, *pw1, *pw2, *pmid;
    float *pcx;
    cudaGetSymbolAddress((void**)&pctx, g_ctxh);
    cudaGetSymbolAddress((void**)&pw1,  g_w1h);
    cudaGetSymbolAddress((void**)&pw2,  g_w2h);
    cudaGetSymbolAddress((void**)&pmid, g_midh);
    cudaGetSymbolAddress((void**)&pcx,  g_cx);

    cudaFuncSetAttribute(conv_gemm<true >, cudaFuncAttributeMaxDynamicSharedMemorySize, SMREQ);
    cudaFuncSetAttribute(conv_gemm<false>, cudaFuncAttributeMaxDynamicSharedMemorySize, SMREQ);

    const int nprep = 4 * NCH1 * CHWH + 4 * NCH2 * CHWH;
    prep_w<<<(nprep + 255) / 256, 256>>>(w_in, w_out, pw1, pw2);
    build_ctx<<<dim3(65, 32), 256>>>(context, indicator, pctx);
    conv_gemm<true ><<<dim3(4, 32, 2), 256, SMREQ>>>(pw1, NCH1, pctx, b_in,  (void*)pmid);
    conv_gemm<false><<<dim3(4, 32, 2), 256, SMREQ>>>(pw2, NCH2, pmid, b_out, (void*)pcx);
    scatter_add<<<40960, 256>>>(global_x, pcx, bbox, out);
}